// round 9
// baseline (speedup 1.0000x reference)
#include <cuda_runtime.h>

// NCELoss: N=4096, E=1024, K=50 noise (+1 target). Output: scalar f32 loss.
//
// Persistent two-phase kernel (E split at 512, global barrier between
// phases keeps the live weight working set ~99 MB < L2 -> ~330 MB DRAM,
// measured in R6/R8). NEW vs R8: the input half-row lives in REGISTERS
// (4 float4/lane covers 512 floats/warp), eliminating the entire smem/LDS
// input stream - which the R1..R8 invariant (~100us regardless of DRAM
// bytes) identified as half the L1tex operand flow. Hot loop does ONLY
// 8 weight LDG.128 per column pair (proven-best MLP) + FFMA + shuffles.
// Last block (self-resetting ticket) reduces partials in double.

#define EDIM   1024
#define HALF   512
#define KNOISE 50
#define NCOLS  (KNOISE + 1)
#define NORM_TERM 9.0f
#define NWARPS 8
#define NTHREADS (NWARPS * 32)
#define MAXN   8192
#define BLOCKS_PER_SM 3
#define GRID_BLOCKS (148 * BLOCKS_PER_SM)   // guaranteed co-resident

__device__ float         g_logit[MAXN * NCOLS];
__device__ double        g_partial[GRID_BLOCKS];
__device__ unsigned int  g_bar  = 0;    // phase barrier counter
__device__ unsigned int  g_done = 0;    // completion ticket

__device__ __forceinline__ float loss_term(int j, int idx, float s,
                                           const float* __restrict__ bias,
                                           const float* __restrict__ noise)
{
    const float logit = s + __ldg(&bias[idx]);
    const float p  = expf(logit - NORM_TERM);
    const float kp = (float)KNOISE * __ldg(&noise[idx]);
    const float num = (j == 0) ? p : kp;   // j==0: data term, else noise term
    return logf(num / (p + kp));
}

__global__ __launch_bounds__(NTHREADS, BLOCKS_PER_SM) void nce_loss_kernel(
    const float* __restrict__ input,
    const int*   __restrict__ target,
    const int*   __restrict__ noise_samples,
    const float* __restrict__ noise,
    const float* __restrict__ weight,
    const float* __restrict__ bias,
    float*       __restrict__ out,
    int N)
{
    __shared__ float  s_wsum[NWARPS];
    __shared__ bool   s_is_last;

    const int tid  = threadIdx.x;
    const int lane = tid & 31;
    const int wid  = tid >> 5;

    float acc = 0.0f;                      // phase-1 loss accumulator (lane 0s)

    #pragma unroll 1
    for (int half = 0; half < 2; half++) {
        const int eoff = half * HALF;

        #pragma unroll 1
        for (int n = blockIdx.x; n < N; n += gridDim.x) {
            // Input half-row -> registers: 4 float4 per lane covers 512 floats.
            const float4* x4 = reinterpret_cast<const float4*>(
                input + (size_t)n * EDIM + eoff);
            float4 xr[4];
            #pragma unroll
            for (int i = 0; i < 4; i++) xr[i] = __ldg(&x4[lane + 32 * i]);

            // Columns in pairs (j, j+8): 8 weight LDG.128 in flight per warp.
            #pragma unroll 1
            for (int j = wid; j < NCOLS; j += 2 * NWARPS) {
                const int  jB   = j + NWARPS;
                const bool hasB = (jB < NCOLS);

                const int idxA = (j == 0)
                    ? __ldg(&target[n])
                    : __ldg(&noise_samples[n * KNOISE + (j - 1)]);
                const int idxB = hasB
                    ? __ldg(&noise_samples[n * KNOISE + (jB - 1)]) : idxA;

                const float4* wA4 = reinterpret_cast<const float4*>(
                    weight + (size_t)idxA * EDIM + eoff);
                const float4* wB4 = reinterpret_cast<const float4*>(
                    weight + (size_t)idxB * EDIM + eoff);

                float4 wA[4], wB[4];
                #pragma unroll
                for (int i = 0; i < 4; i++) wA[i] = __ldg(&wA4[lane + 32 * i]);
                #pragma unroll
                for (int i = 0; i < 4; i++) wB[i] = __ldg(&wB4[lane + 32 * i]);

                float sA = 0.0f, sB = 0.0f;
                #pragma unroll
                for (int i = 0; i < 4; i++) {
                    sA += wA[i].x * xr[i].x + wA[i].y * xr[i].y
                        + wA[i].z * xr[i].z + wA[i].w * xr[i].w;
                    sB += wB[i].x * xr[i].x + wB[i].y * xr[i].y
                        + wB[i].z * xr[i].z + wB[i].w * xr[i].w;
                }
                #pragma unroll
                for (int o = 16; o; o >>= 1) {
                    sA += __shfl_xor_sync(0xffffffffu, sA, o);
                    sB += __shfl_xor_sync(0xffffffffu, sB, o);
                }

                if (lane == 0) {
                    if (half == 0) {
                        g_logit[n * NCOLS + j] = sA;
                        if (hasB) g_logit[n * NCOLS + jB] = sB;
                    } else {
                        acc += loss_term(j, idxA, g_logit[n * NCOLS + j] + sA,
                                         bias, noise);
                        if (hasB)
                            acc += loss_term(jB, idxB,
                                             g_logit[n * NCOLS + jB] + sB,
                                             bias, noise);
                    }
                }
            }
        }

        // Global phase barrier (performance fence; grid is co-resident).
        if (half == 0) {
            if (tid == 0) {
                atomicAdd(&g_bar, 1u);
                while (true) {
                    unsigned int v;
                    asm volatile("ld.global.cg.u32 %0, [%1];"
                                 : "=r"(v) : "l"(&g_bar));
                    if (v >= gridDim.x) break;
                    __nanosleep(128);
                }
            }
            __syncthreads();
        }
    }

    // Block partial -> global.
    if (lane == 0) s_wsum[wid] = acc;
    __syncthreads();
    if (wid == 0) {
        float v = (lane < NWARPS) ? s_wsum[lane] : 0.0f;
        #pragma unroll
        for (int o = NWARPS / 2; o; o >>= 1) v += __shfl_xor_sync(0xffffffffu, v, o);
        if (lane == 0) g_partial[blockIdx.x] = (double)v;
    }

    // Completion ticket: last block reduces, writes out, resets state.
    if (tid == 0) {
        __threadfence();
        unsigned int prev = atomicAdd(&g_done, 1u);
        s_is_last = (prev == gridDim.x - 1);
    }
    __syncthreads();

    if (s_is_last) {
        double d = 0.0;
        for (int i = tid; i < (int)gridDim.x; i += NTHREADS) {
            double val;
            asm volatile("ld.global.cg.f64 %0, [%1];"
                         : "=d"(val) : "l"(g_partial + i));
            d += val;
        }
        #pragma unroll
        for (int o = 16; o; o >>= 1) d += __shfl_xor_sync(0xffffffffu, d, o);
        __shared__ double s_dsum[NWARPS];
        if (lane == 0) s_dsum[wid] = d;
        __syncthreads();
        if (wid == 0) {
            double t = (lane < NWARPS) ? s_dsum[lane] : 0.0;
            #pragma unroll
            for (int o = NWARPS / 2; o; o >>= 1)
                t += __shfl_xor_sync(0xffffffffu, t, o);
            if (lane == 0) {
                out[0]  = (float)(-t / (double)N);
                g_done  = 0u;               // reset for graph replay
                g_bar   = 0u;
            }
        }
    }
}

extern "C" void kernel_launch(void* const* d_in, const int* in_sizes, int n_in,
                              void* d_out, int out_size) {
    const float* input         = (const float*)d_in[0];
    const int*   target        = (const int*)  d_in[1];
    const int*   noise_samples = (const int*)  d_in[2];
    const float* noise         = (const float*)d_in[3];
    const float* weight        = (const float*)d_in[4];
    const float* bias          = (const float*)d_in[5];
    float* out = (float*)d_out;

    const int N = in_sizes[1];  // number of examples

    int grid = GRID_BLOCKS;
    if (grid > N) grid = N;

    nce_loss_kernel<<<grid, NTHREADS>>>(input, target, noise_samples, noise,
                                        weight, bias, out, N);
}